// round 15
// baseline (speedup 1.0000x reference)
#include <cuda_runtime.h>
#include <cuda_bf16.h>
#include <mma.h>
#include <cstdint>
#include <cstddef>

using namespace nvcuda;

#define N_NODES 32768
#define E_EDGES 524288
#define DIM     512
#define NGRAPH  512

// ---------------- scratch (static device arrays; no allocation) ----------------
__device__ __align__(128) __nv_bfloat16 g_S16[N_NODES * DIM];  // 32 MB GEMM0 output (bf16)
__device__ __align__(128) __nv_bfloat16 g_H16[N_NODES * DIM];  // 32 MB hidden h (bf16)
__device__ __align__(128) __nv_bfloat16 g_AH[N_NODES * DIM];   // 32 MB feat-hi
__device__ __align__(128) __nv_bfloat16 g_AL[N_NODES * DIM];   // 32 MB feat-lo
__device__ __align__(128) float g_P0 [NGRAPH * DIM];
__device__ __align__(128) float g_GS [NGRAPH * DIM];
__device__ __align__(128) float g_Z1 [NGRAPH * DIM];
__device__ __align__(128) float g_Z2 [NGRAPH * DIM];
__device__ __align__(128) float g_ZS [NGRAPH * DIM];
// W0 hi: [n][k] bf16, K-major (== wmma col_major B)
__device__ __align__(128) __nv_bfloat16 g_WT0[DIM * DIM];
// CSR (dst-sorted edges)
__device__ __align__(128) int   g_deg [N_NODES];
__device__ __align__(128) int   g_off [N_NODES + 1];
__device__ __align__(128) int   g_cur [N_NODES];
__device__ __align__(128) int   g_esrc[E_EDGES];
__device__ __align__(128) float g_eval[E_EDGES];

__device__ __forceinline__ uint32_t pack_bf2(float a, float b) {
    __nv_bfloat162 t = __floats2bfloat162_rn(a, b);
    return *reinterpret_cast<uint32_t*>(&t);
}
__device__ __forceinline__ void split4(float4 v, uint2& hv, uint2& lv) {
    float hx = __bfloat162float(__float2bfloat16(v.x));
    float hy = __bfloat162float(__float2bfloat16(v.y));
    float hz = __bfloat162float(__float2bfloat16(v.z));
    float hw = __bfloat162float(__float2bfloat16(v.w));
    hv.x = pack_bf2(v.x, v.y);           hv.y = pack_bf2(v.z, v.w);
    lv.x = pack_bf2(v.x - hx, v.y - hy); lv.y = pack_bf2(v.z - hz, v.w - hw);
}

// ================= fused prep: W0 hi-transpose + feat split + deg zero =================
__global__ void __launch_bounds__(256)
prep_all(const float* __restrict__ W0, __nv_bfloat16* __restrict__ WT0,
         const float* __restrict__ X,
         __nv_bfloat16* __restrict__ AH, __nv_bfloat16* __restrict__ AL)
{
    int b = blockIdx.x;
    if (b < 1024) {                       // W0 hi: DIM*DIM elems, transpose to [n][k]
        int i = b * 256 + threadIdx.x;
        int k = i / DIM, n = i % DIM;
        WT0[(size_t)n * DIM + k] = __float2bfloat16(W0[i]);
    } else if (b < 1024 + 16384) {        // feat split: N*D/4 float4s
        int i = (b - 1024) * 256 + threadIdx.x;
        float4 v = ((const float4*)X)[i];
        uint2 hv, lv;
        split4(v, hv, lv);
        ((uint2*)AH)[i] = hv;
        ((uint2*)AL)[i] = lv;
    } else {                              // deg zero: 8192 int4s
        int i = (b - 17408) * 256 + threadIdx.x;
        ((int4*)g_deg)[i] = make_int4(0, 0, 0, 0);
    }
}

// ================= CSR build =================
__global__ void hist_k(const int* __restrict__ dst) {
    int e = blockIdx.x * blockDim.x + threadIdx.x;
    if (e < E_EDGES) atomicAdd(&g_deg[dst[e]], 1);
}

__global__ void scan_k() {                 // 1024 threads, shuffle-based hierarchical scan
    __shared__ int wtot[32];
    int t = threadIdx.x, lane = t & 31, w = t >> 5;
    int base = t * 32;
    int v[32];
#pragma unroll
    for (int q = 0; q < 8; q++) {
        int4 x = *(const int4*)&g_deg[base + q * 4];
        v[q * 4 + 0] = x.x; v[q * 4 + 1] = x.y; v[q * 4 + 2] = x.z; v[q * 4 + 3] = x.w;
    }
    int local[32];
    int s = 0;
#pragma unroll
    for (int i = 0; i < 32; i++) { local[i] = s; s += v[i]; }
    int sc = s;
#pragma unroll
    for (int d = 1; d < 32; d <<= 1) {
        int u = __shfl_up_sync(0xFFFFFFFFu, sc, d);
        if (lane >= d) sc += u;
    }
    if (lane == 31) wtot[w] = sc;
    __syncthreads();
    if (w == 0) {
        int x = wtot[lane];
#pragma unroll
        for (int d = 1; d < 32; d <<= 1) {
            int u = __shfl_up_sync(0xFFFFFFFFu, x, d);
            if (lane >= d) x += u;
        }
        wtot[lane] = x;
    }
    __syncthreads();
    int pre = sc - s + (w ? wtot[w - 1] : 0);
#pragma unroll
    for (int i = 0; i < 32; i++) {
        int o = pre + local[i];
        g_off[base + i] = o;
        g_cur[base + i] = o;
    }
    if (t == 1023) g_off[N_NODES] = wtot[31];
}

__global__ void scat_k(const int* __restrict__ dst, const int* __restrict__ src,
                       const float* __restrict__ adj) {
    int e = blockIdx.x * blockDim.x + threadIdx.x;
    if (e >= E_EDGES) return;
    int p = atomicAdd(&g_cur[dst[e]], 1);
    g_esrc[p] = src[e];
    g_eval[p] = adj[e];
}

// ====== bf16 gather core: bit-op expand (SHF/LOP), fp32 accumulate ======
__device__ __forceinline__ void fma_bf16x2(float a[16], float v, uint4 x0, uint4 x1) {
    const uint32_t* u0 = (const uint32_t*)&x0;
    const uint32_t* u1 = (const uint32_t*)&x1;
#pragma unroll
    for (int k = 0; k < 4; k++) {
        float f0 = __uint_as_float(u0[k] << 16);
        float f1 = __uint_as_float(u0[k] & 0xFFFF0000u);
        a[2 * k]     = fmaf(v, f0, a[2 * k]);
        a[2 * k + 1] = fmaf(v, f1, a[2 * k + 1]);
        f0 = __uint_as_float(u1[k] << 16);
        f1 = __uint_as_float(u1[k] & 0xFFFF0000u);
        a[8 + 2 * k]     = fmaf(v, f0, a[8 + 2 * k]);
        a[8 + 2 * k + 1] = fmaf(v, f1, a[8 + 2 * k + 1]);
    }
}

__device__ __forceinline__ void gather_row16(const uint4* __restrict__ Sb,
                                             int j0, int j1, float a[16]) {
#pragma unroll
    for (int m = 0; m < 16; m++) a[m] = 0.f;
    int j = j0;
    for (; j + 3 < j1; j += 4) {
        int   s0 = __ldg(&g_esrc[j]);
        int   s1 = __ldg(&g_esrc[j + 1]);
        int   s2 = __ldg(&g_esrc[j + 2]);
        int   s3 = __ldg(&g_esrc[j + 3]);
        float v0 = __ldg(&g_eval[j]);
        float v1 = __ldg(&g_eval[j + 1]);
        float v2 = __ldg(&g_eval[j + 2]);
        float v3 = __ldg(&g_eval[j + 3]);
        const uint4* r0 = Sb + (size_t)s0 * 64;
        const uint4* r1 = Sb + (size_t)s1 * 64;
        const uint4* r2 = Sb + (size_t)s2 * 64;
        const uint4* r3 = Sb + (size_t)s3 * 64;
        uint4 x00 = r0[0], x01 = r0[32];
        uint4 x10 = r1[0], x11 = r1[32];
        uint4 x20 = r2[0], x21 = r2[32];
        uint4 x30 = r3[0], x31 = r3[32];
        fma_bf16x2(a, v0, x00, x01);
        fma_bf16x2(a, v1, x10, x11);
        fma_bf16x2(a, v2, x20, x21);
        fma_bf16x2(a, v3, x30, x31);
    }
    for (; j < j1; j++) {
        int   s0 = __ldg(&g_esrc[j]);
        float v0 = __ldg(&g_eval[j]);
        const uint4* r0 = Sb + (size_t)s0 * 64;
        fma_bf16x2(a, v0, r0[0], r0[32]);
    }
}

// ---- layer-0 gather: H16[node] = bf16(relu(sum adj*S16[src] + b0)) ----
__global__ void __launch_bounds__(256)
gather_relu_k(const __nv_bfloat16* __restrict__ S16, __nv_bfloat16* __restrict__ H16,
              const float* __restrict__ bias)
{
    int w = threadIdx.x >> 5, lane = threadIdx.x & 31;
    int node = blockIdx.x * 8 + w;
    float a[16];
    gather_row16((const uint4*)S16 + lane, g_off[node], g_off[node + 1], a);
    float4 bv[4];
    bv[0] = __ldg((const float4*)bias + 2 * lane);
    bv[1] = __ldg((const float4*)bias + 2 * lane + 1);
    bv[2] = __ldg((const float4*)bias + 64 + 2 * lane);
    bv[3] = __ldg((const float4*)bias + 64 + 2 * lane + 1);
    const float* bb = (const float*)bv;
    uint4 o0, o1;
    uint32_t* p0 = (uint32_t*)&o0;
    uint32_t* p1 = (uint32_t*)&o1;
#pragma unroll
    for (int k = 0; k < 4; k++) {
        float e0 = fmaxf(a[2 * k]     + bb[2 * k], 0.f);
        float e1 = fmaxf(a[2 * k + 1] + bb[2 * k + 1], 0.f);
        p0[k] = pack_bf2(e0, e1);
        e0 = fmaxf(a[8 + 2 * k]     + bb[8 + 2 * k], 0.f);
        e1 = fmaxf(a[8 + 2 * k + 1] + bb[8 + 2 * k + 1], 0.f);
        p1[k] = pack_bf2(e0, e1);
    }
    *((uint4*)H16 + (size_t)node * 64 + lane)      = o0;
    *((uint4*)H16 + (size_t)node * 64 + 32 + lane) = o1;
}

// ---- edge pool: P0[g] = (1/64) * sum_{e: dst in graph g} adj_e * H16[src_e] ----
__global__ void __launch_bounds__(256)
edgepool_k(const __nv_bfloat16* __restrict__ H16, float* __restrict__ P0)
{
    __shared__ float4 red[8][128];
    int g = blockIdx.x;
    int w = threadIdx.x >> 5, lane = threadIdx.x & 31;
    int j0 = g_off[g * 64], j1 = g_off[g * 64 + 64];
    float a[16];
#pragma unroll
    for (int m = 0; m < 16; m++) a[m] = 0.f;
    const uint4* Hb = (const uint4*)H16 + lane;
    int j = j0 + w;
    for (; j + 8 < j1; j += 16) {
        int   s0 = __ldg(&g_esrc[j]);
        int   s1 = __ldg(&g_esrc[j + 8]);
        float v0 = __ldg(&g_eval[j]);
        float v1 = __ldg(&g_eval[j + 8]);
        const uint4* r0 = Hb + (size_t)s0 * 64;
        const uint4* r1 = Hb + (size_t)s1 * 64;
        uint4 x00 = r0[0], x01 = r0[32];
        uint4 x10 = r1[0], x11 = r1[32];
        fma_bf16x2(a, v0, x00, x01);
        fma_bf16x2(a, v1, x10, x11);
    }
    if (j < j1) {
        int   s0 = __ldg(&g_esrc[j]);
        float v0 = __ldg(&g_eval[j]);
        const uint4* r0 = Hb + (size_t)s0 * 64;
        fma_bf16x2(a, v0, r0[0], r0[32]);
    }
    red[w][2 * lane]          = make_float4(a[0], a[1], a[2], a[3]);
    red[w][2 * lane + 1]      = make_float4(a[4], a[5], a[6], a[7]);
    red[w][64 + 2 * lane]     = make_float4(a[8], a[9], a[10], a[11]);
    red[w][64 + 2 * lane + 1] = make_float4(a[12], a[13], a[14], a[15]);
    __syncthreads();
    if (threadIdx.x < 128) {
        int c4 = threadIdx.x;
        float4 s = red[0][c4];
#pragma unroll
        for (int q = 1; q < 8; q++) {
            float4 t = red[q][c4];
            s.x += t.x; s.y += t.y; s.z += t.z; s.w += t.w;
        }
        s.x *= (1.f / 64.f); s.y *= (1.f / 64.f);
        s.z *= (1.f / 64.f); s.w *= (1.f / 64.f);
        ((float4*)P0)[(size_t)g * 128 + c4] = s;
    }
}

// ======== wmma bf16x2 GEMM (A = hi+lo, B = hi), 2 CTAs/SM, 3-stage cp.async ========
// CTA 128(M) x 128(N); 8 warps as 4(m) x 2(n); warp tile 32x64; BK=32; bf16 output.
static constexpr int LDA   = 40;
static constexpr int A_TSZ = 128 * LDA;                  // 5120 elems per tile
static constexpr int STG   = 3 * A_TSZ;                  // A-hi, A-lo, B-hi
static constexpr int SMEM_GEMM = 3 * STG * 2;            // 92160 bytes (3 stages)
__device__ __forceinline__ void cp16(uint32_t s, const void* g) {
    asm volatile("cp.async.cg.shared.global [%0], [%1], 16;" :: "r"(s), "l"(g));
}
__global__ void __launch_bounds__(256, 2)
gemm_bf2(const __nv_bfloat16* __restrict__ AH, const __nv_bfloat16* __restrict__ AL,
         const __nv_bfloat16* __restrict__ WT, __nv_bfloat16* __restrict__ C16)
{
    extern __shared__ __nv_bfloat16 sm[];
    const uint32_t smb = (uint32_t)__cvta_generic_to_shared(sm);
    const int tid = threadIdx.x;
    const int wid = tid >> 5;
    const int lane = tid & 31;
    const int m0 = blockIdx.y * 128;
    const int n0 = blockIdx.x * 128;
    const int wm = (wid >> 1) * 32;
    const int wn = (wid & 1) * 64;
    constexpr int NITER = DIM / 32;

    auto load_stage = [&](int kc, int s) {
        const uint32_t sb = smb + s * STG * 2;
#pragma unroll
        for (int t = 0; t < 2; t++) {
            const __nv_bfloat16* src = t ? AL : AH;
#pragma unroll
            for (int it = 0; it < 2; it++) {
                int c = tid + it * 256;
                int row = c >> 2, seg = c & 3;
                cp16(sb + (t * A_TSZ + row * LDA + seg * 8) * 2,
                     src + (size_t)(m0 + row) * DIM + kc * 32 + seg * 8);
            }
        }
#pragma unroll
        for (int it = 0; it < 2; it++) {
            int c = tid + it * 256;
            int row = c >> 2, seg = c & 3;
            cp16(sb + (2 * A_TSZ + row * LDA + seg * 8) * 2,
                 WT + (size_t)(n0 + row) * DIM + kc * 32 + seg * 8);
        }
        asm volatile("cp.async.commit_group;");
    };

    wmma::fragment<wmma::accumulator, 16, 16, 16, float> acc[2][4];
#pragma unroll
    for (int i = 0; i < 2; i++)
#pragma unroll
        for (int j = 0; j < 4; j++) wmma::fill_fragment(acc[i][j], 0.f);

    load_stage(0, 0);
    load_stage(1, 1);

    for (int kc = 0; kc < NITER; kc++) {
        const int st = kc % 3;
        if (kc + 2 < NITER) {
            asm volatile("cp.async.wait_group 1;");   // stage kc landed; newest may fly
        } else {
            asm volatile("cp.async.wait_group 0;");   // drain at the tail
        }
        __syncthreads();   // all warps see stage st; compute on stage (kc+2)%3 finished
        if (kc + 2 < NITER) load_stage(kc + 2, (kc + 2) % 3);

        const __nv_bfloat16* Ah = &sm[st * STG];
        const __nv_bfloat16* Al = Ah + A_TSZ;
        const __nv_bfloat16* Bh = Ah + 2 * A_TSZ;
#pragma unroll
        for (int ks = 0; ks < 2; ks++) {
            const int kk = ks * 16;
            wmma::fragment<wmma::matrix_a, 16, 16, 16, __nv_bfloat16, wmma::row_major> ah[2], al[2];
#pragma unroll
            for (int i = 0; i < 2; i++) {
                wmma::load_matrix_sync(ah[i], Ah + (wm + 16 * i) * LDA + kk, LDA);
                wmma::load_matrix_sync(al[i], Al + (wm + 16 * i) * LDA + kk, LDA);
            }
#pragma unroll
            for (int j = 0; j < 4; j++) {      // stream one B fragment at a time
                wmma::fragment<wmma::matrix_b, 16, 16, 16, __nv_bfloat16, wmma::col_major> bh;
                wmma::load_matrix_sync(bh, Bh + (wn + 16 * j) * LDA + kk, LDA);
#pragma unroll
                for (int i = 0; i < 2; i++) {
                    wmma::mma_sync(acc[i][j], ah[i], bh, acc[i][j]);
                    wmma::mma_sync(acc[i][j], al[i], bh, acc[i][j]);
                }
            }
        }
    }

    // bf16 epilogue via per-warp smem staging (16x64 fp32 = 4KB per warp)
    __syncthreads();
    float* stage = reinterpret_cast<float*>(sm) + wid * 1024;
#pragma unroll
    for (int i = 0; i < 2; i++) {
#pragma unroll
        for (int j = 0; j < 4; j++)
            wmma::store_matrix_sync(stage + 16 * j, acc[i][j], 64, wmma::mem_row_major);
        __syncwarp();
#pragma unroll
        for (int q = 0; q < 4; q++) {
            int chunk = lane + 32 * q;           // 0..127
            int r = chunk >> 3, p = chunk & 7;   // 16 rows x 8 chunks
            float4 f0 = *(float4*)(stage + r * 64 + p * 8);
            float4 f1 = *(float4*)(stage + r * 64 + p * 8 + 4);
            uint4 hv;
            ((uint32_t*)&hv)[0] = pack_bf2(f0.x, f0.y);
            ((uint32_t*)&hv)[1] = pack_bf2(f0.z, f0.w);
            ((uint32_t*)&hv)[2] = pack_bf2(f1.x, f1.y);
            ((uint32_t*)&hv)[3] = pack_bf2(f1.z, f1.w);
            *(uint4*)(C16 + (size_t)(m0 + wm + 16 * i + r) * DIM + n0 + wn + p * 8) = hv;
        }
        __syncwarp();
    }
}

// ================= small fp32 GEMM core, cp.async double-buffered =================
// 32x64 tile, 256 threads (16x16, 2x4 micro), BK=32, K=DIM=512.
struct SmemS { float As[2][32][36]; float Bs[2][32][64]; };

template<int ACT, bool CA, bool EXPAND>
__device__ __forceinline__ void small_gemm_core(
    SmemS& smem,
    const float* __restrict__ A, const float* __restrict__ B,
    const float* __restrict__ bias, const float* __restrict__ cadd,
    float* __restrict__ C, int bm0, int bn0)
{
    const int tid = threadIdx.x;
    const int tx = tid & 15, ty = tid >> 4;
    float acc[2][4];
#pragma unroll
    for (int i = 0; i < 2; i++)
#pragma unroll
        for (int j = 0; j < 4; j++) acc[i][j] = 0.f;

    auto load = [&](int kc, int s) {
        {
            int c = tid;
            int row = c >> 3, seg = c & 7;
            cp16((uint32_t)__cvta_generic_to_shared(&smem.As[s][row][seg * 4]),
                 A + (size_t)(bm0 + row) * DIM + kc * 32 + seg * 4);
        }
#pragma unroll
        for (int it = 0; it < 2; it++) {
            int c = tid + it * 256;
            int row = c >> 4, seg = c & 15;
            cp16((uint32_t)__cvta_generic_to_shared(&smem.Bs[s][row][seg * 4]),
                 B + (size_t)(kc * 32 + row) * DIM + bn0 + seg * 4);
        }
        asm volatile("cp.async.commit_group;");
    };

    load(0, 0);
    for (int kc = 0; kc < DIM / 32; kc++) {
        const int st = kc & 1;
        asm volatile("cp.async.wait_group 0;");
        __syncthreads();
        if (kc + 1 < DIM / 32) load(kc + 1, st ^ 1);
#pragma unroll
        for (int kk = 0; kk < 32; kk++) {
            float ra[2], rb[4];
#pragma unroll
            for (int i = 0; i < 2; i++) ra[i] = smem.As[st][ty * 2 + i][kk];
            *(float4*)rb = *(const float4*)&smem.Bs[st][kk][tx * 4];
#pragma unroll
            for (int i = 0; i < 2; i++)
#pragma unroll
                for (int j = 0; j < 4; j++)
                    acc[i][j] = fmaf(ra[i], rb[j], acc[i][j]);
        }
    }

#pragma unroll
    for (int i = 0; i < 2; i++) {
        int m = bm0 + ty * 2 + i;
        int n = bn0 + tx * 4;
        float4 v = make_float4(acc[i][0], acc[i][1], acc[i][2], acc[i][3]);
        float4 bv = *(const float4*)(bias + n);
        v.x += bv.x; v.y += bv.y; v.z += bv.z; v.w += bv.w;
        if (ACT == 1) {
            v.x = fmaxf(v.x, 0.f); v.y = fmaxf(v.y, 0.f);
            v.z = fmaxf(v.z, 0.f); v.w = fmaxf(v.w, 0.f);
        }
        if (ACT == 2) {
            v.x = 1.f / (1.f + __expf(-v.x)); v.y = 1.f / (1.f + __expf(-v.y));
            v.z = 1.f / (1.f + __expf(-v.z)); v.w = 1.f / (1.f + __expf(-v.w));
        }
        if (CA) {
            float4 av = *(const float4*)(cadd + (size_t)m * DIM + n);
            v.x += av.x; v.y += av.y; v.z += av.z; v.w += av.w;
        }
        if (EXPAND) {
            float* base = C + (size_t)m * 64 * DIM + n;
#pragma unroll 8
            for (int rep = 0; rep < 64; rep++)
                *(float4*)(base + (size_t)rep * DIM) = v;
        } else {
            *(float4*)(C + (size_t)m * DIM + n) = v;
        }
    }
}

template<int ACT>
__global__ void __launch_bounds__(256)
gemm_s(const float* __restrict__ A, const float* __restrict__ B,
       const float* __restrict__ bias, float* __restrict__ C)
{
    __shared__ SmemS smem;
    small_gemm_core<ACT, false, false>(smem, A, B, bias, nullptr, C,
                                       blockIdx.y * 32, blockIdx.x * 64);
}

__global__ void __launch_bounds__(256)
gemm_dual(const float* __restrict__ A,
          const float* __restrict__ B0, const float* __restrict__ bias0, float* __restrict__ C0,
          const float* __restrict__ B1, const float* __restrict__ bias1, float* __restrict__ C1)
{
    __shared__ SmemS smem;
    if (blockIdx.z == 0)
        small_gemm_core<1, false, false>(smem, A, B0, bias0, nullptr, C0,
                                         blockIdx.y * 32, blockIdx.x * 64);
    else
        small_gemm_core<0, false, false>(smem, A, B1, bias1, nullptr, C1,
                                         blockIdx.y * 32, blockIdx.x * 64);
}

__global__ void __launch_bounds__(256)
gemm_final(const float* __restrict__ A, const float* __restrict__ B,
           const float* __restrict__ bias, const float* __restrict__ cadd,
           float* __restrict__ out)
{
    __shared__ SmemS smem;
    small_gemm_core<1, true, true>(smem, A, B, bias, cadd, out,
                                   blockIdx.y * 32, blockIdx.x * 64);
}

// ---------------- launch ----------------
extern "C" void kernel_launch(void* const* d_in, const int* in_sizes, int n_in,
                              void* d_out, int out_size)
{
    const float* feat = (const float*)d_in[0];
    const int*   src  = (const int*)  d_in[1];
    const int*   dst  = (const int*)  d_in[2];
    const float* adj  = (const float*)d_in[3];
    const float* W0   = (const float*)d_in[5];
    const float* b0   = (const float*)d_in[6];
    const float* W1   = (const float*)d_in[7];
    const float* b1   = (const float*)d_in[8];
    const float* gW1  = (const float*)d_in[9];
    const float* gb1  = (const float*)d_in[10];
    const float* gW2  = (const float*)d_in[11];
    const float* gb2  = (const float*)d_in[12];
    const float* gW3  = (const float*)d_in[13];
    const float* gb3  = (const float*)d_in[14];
    const float* gWs  = (const float*)d_in[15];
    const float* gbs  = (const float*)d_in[16];
    float* out = (float*)d_out;

    float *P0, *GS, *Z1, *Z2, *ZS;
    __nv_bfloat16 *S16, *H16, *WT0, *AH, *AL;
    cudaGetSymbolAddress((void**)&S16, g_S16);
    cudaGetSymbolAddress((void**)&H16, g_H16);
    cudaGetSymbolAddress((void**)&P0,  g_P0);
    cudaGetSymbolAddress((void**)&GS,  g_GS);
    cudaGetSymbolAddress((void**)&Z1,  g_Z1);
    cudaGetSymbolAddress((void**)&Z2,  g_Z2);
    cudaGetSymbolAddress((void**)&ZS,  g_ZS);
    cudaGetSymbolAddress((void**)&WT0, g_WT0);
    cudaGetSymbolAddress((void**)&AH,  g_AH);
    cudaGetSymbolAddress((void**)&AL,  g_AL);

    cudaFuncSetAttribute(gemm_bf2, cudaFuncAttributeMaxDynamicSharedMemorySize, SMEM_GEMM);

    dim3 gw(DIM / 128, N_NODES / 128);
    dim3 gsm(DIM / 64, NGRAPH / 32);
    dim3 gdual(DIM / 64, NGRAPH / 32, 2);

    // 1: fused prep (W0 hi transpose + feat split + deg zero)
    prep_all<<<17440, 256>>>(W0, WT0, feat, AH, AL);
    // 2-3: CSR histogram + scan
    hist_k<<<E_EDGES / 256, 256>>>(dst);
    scan_k<<<1, 1024>>>();
    // 4: GCN layer 0 GEMM (profiled slot)
    gemm_bf2<<<gw, 256, SMEM_GEMM>>>(AH, AL, WT0, S16);
    // 5: CSR scatter
    scat_k<<<E_EDGES / 256, 256>>>(dst, src, adj);
    // 6: H16 = bf16(relu(A_hat@S16 + b0))
    gather_relu_k<<<N_NODES / 8, 256>>>(S16, H16, b0);
    // 7: layer-1 collapsed through pooling
    edgepool_k<<<NGRAPH, 256>>>(H16, P0);
    // 8-11: pooled tail
    gemm_s<2><<<gsm, 256>>>(P0, W1, b1, GS);                       // GS = sigmoid(P0@W1+b1)
    gemm_dual<<<gdual, 256>>>(GS, gW1, gb1, Z1, gWs, gbs, ZS);     // Z1 & shortcut ZS
    gemm_s<1><<<gsm, 256>>>(Z1, gW2, gb2, Z2);                     // Z2
    gemm_final<<<gsm, 256>>>(Z2, gW3, gb3, ZS, out);               // relu(+b3)+ZS, expand
}

// round 16
// speedup vs baseline: 1.4430x; 1.4430x over previous
#include <cuda_runtime.h>
#include <cuda_bf16.h>
#include <mma.h>
#include <cstdint>
#include <cstddef>

using namespace nvcuda;

#define N_NODES 32768
#define E_EDGES 524288
#define DIM     512
#define NGRAPH  512

// ---------------- scratch (static device arrays; no allocation) ----------------
__device__ __align__(128) __nv_bfloat16 g_S16[N_NODES * DIM];  // 32 MB GEMM0 output (bf16)
__device__ __align__(128) __nv_bfloat16 g_H16[N_NODES * DIM];  // 32 MB hidden h (bf16)
__device__ __align__(128) __nv_bfloat16 g_AH[N_NODES * DIM];   // 32 MB feat-hi
__device__ __align__(128) __nv_bfloat16 g_AL[N_NODES * DIM];   // 32 MB feat-lo
__device__ __align__(128) float g_P0 [NGRAPH * DIM];
__device__ __align__(128) float g_GS [NGRAPH * DIM];
__device__ __align__(128) float g_Z1 [NGRAPH * DIM];
__device__ __align__(128) float g_Z2 [NGRAPH * DIM];
__device__ __align__(128) float g_ZS [NGRAPH * DIM];
// W0 hi: [n][k] bf16, K-major (== wmma col_major B)
__device__ __align__(128) __nv_bfloat16 g_WT0[DIM * DIM];
// CSR (dst-sorted edges)
__device__ __align__(128) int   g_deg [N_NODES];
__device__ __align__(128) int   g_off [N_NODES + 1];
__device__ __align__(128) int   g_cur [N_NODES];
__device__ __align__(128) int   g_esrc[E_EDGES];
__device__ __align__(128) float g_eval[E_EDGES];

__device__ __forceinline__ uint32_t pack_bf2(float a, float b) {
    __nv_bfloat162 t = __floats2bfloat162_rn(a, b);
    return *reinterpret_cast<uint32_t*>(&t);
}
__device__ __forceinline__ void split4(float4 v, uint2& hv, uint2& lv) {
    float hx = __bfloat162float(__float2bfloat16(v.x));
    float hy = __bfloat162float(__float2bfloat16(v.y));
    float hz = __bfloat162float(__float2bfloat16(v.z));
    float hw = __bfloat162float(__float2bfloat16(v.w));
    hv.x = pack_bf2(v.x, v.y);           hv.y = pack_bf2(v.z, v.w);
    lv.x = pack_bf2(v.x - hx, v.y - hy); lv.y = pack_bf2(v.z - hz, v.w - hw);
}

// ================= fused prep: W0 hi-transpose + feat split + deg zero =================
__global__ void __launch_bounds__(256)
prep_all(const float* __restrict__ W0, __nv_bfloat16* __restrict__ WT0,
         const float* __restrict__ X,
         __nv_bfloat16* __restrict__ AH, __nv_bfloat16* __restrict__ AL)
{
    int b = blockIdx.x;
    if (b < 1024) {                       // W0 hi: DIM*DIM elems, transpose to [n][k]
        int i = b * 256 + threadIdx.x;
        int k = i / DIM, n = i % DIM;
        WT0[(size_t)n * DIM + k] = __float2bfloat16(W0[i]);
    } else if (b < 1024 + 16384) {        // feat split: N*D/4 float4s
        int i = (b - 1024) * 256 + threadIdx.x;
        float4 v = ((const float4*)X)[i];
        uint2 hv, lv;
        split4(v, hv, lv);
        ((uint2*)AH)[i] = hv;
        ((uint2*)AL)[i] = lv;
    } else {                              // deg zero: 8192 int4s
        int i = (b - 17408) * 256 + threadIdx.x;
        ((int4*)g_deg)[i] = make_int4(0, 0, 0, 0);
    }
}

// ================= CSR build =================
__global__ void hist_k(const int* __restrict__ dst) {
    int e = blockIdx.x * blockDim.x + threadIdx.x;
    if (e < E_EDGES) atomicAdd(&g_deg[dst[e]], 1);
}

__global__ void scan_k() {                 // 1024 threads, shuffle-based hierarchical scan
    __shared__ int wtot[32];
    int t = threadIdx.x, lane = t & 31, w = t >> 5;
    int base = t * 32;
    int v[32];
#pragma unroll
    for (int q = 0; q < 8; q++) {
        int4 x = *(const int4*)&g_deg[base + q * 4];
        v[q * 4 + 0] = x.x; v[q * 4 + 1] = x.y; v[q * 4 + 2] = x.z; v[q * 4 + 3] = x.w;
    }
    int local[32];
    int s = 0;
#pragma unroll
    for (int i = 0; i < 32; i++) { local[i] = s; s += v[i]; }
    int sc = s;
#pragma unroll
    for (int d = 1; d < 32; d <<= 1) {
        int u = __shfl_up_sync(0xFFFFFFFFu, sc, d);
        if (lane >= d) sc += u;
    }
    if (lane == 31) wtot[w] = sc;
    __syncthreads();
    if (w == 0) {
        int x = wtot[lane];
#pragma unroll
        for (int d = 1; d < 32; d <<= 1) {
            int u = __shfl_up_sync(0xFFFFFFFFu, x, d);
            if (lane >= d) x += u;
        }
        wtot[lane] = x;
    }
    __syncthreads();
    int pre = sc - s + (w ? wtot[w - 1] : 0);
#pragma unroll
    for (int i = 0; i < 32; i++) {
        int o = pre + local[i];
        g_off[base + i] = o;
        g_cur[base + i] = o;
    }
    if (t == 1023) g_off[N_NODES] = wtot[31];
}

__global__ void scat_k(const int* __restrict__ dst, const int* __restrict__ src,
                       const float* __restrict__ adj) {
    int e = blockIdx.x * blockDim.x + threadIdx.x;
    if (e >= E_EDGES) return;
    int p = atomicAdd(&g_cur[dst[e]], 1);
    g_esrc[p] = src[e];
    g_eval[p] = adj[e];
}

// ====== bf16 gather core: bit-op expand (SHF/LOP), fp32 accumulate ======
__device__ __forceinline__ void fma_bf16x2(float a[16], float v, uint4 x0, uint4 x1) {
    const uint32_t* u0 = (const uint32_t*)&x0;
    const uint32_t* u1 = (const uint32_t*)&x1;
#pragma unroll
    for (int k = 0; k < 4; k++) {
        float f0 = __uint_as_float(u0[k] << 16);
        float f1 = __uint_as_float(u0[k] & 0xFFFF0000u);
        a[2 * k]     = fmaf(v, f0, a[2 * k]);
        a[2 * k + 1] = fmaf(v, f1, a[2 * k + 1]);
        f0 = __uint_as_float(u1[k] << 16);
        f1 = __uint_as_float(u1[k] & 0xFFFF0000u);
        a[8 + 2 * k]     = fmaf(v, f0, a[8 + 2 * k]);
        a[8 + 2 * k + 1] = fmaf(v, f1, a[8 + 2 * k + 1]);
    }
}

__device__ __forceinline__ void gather_row16(const uint4* __restrict__ Sb,
                                             int j0, int j1, float a[16]) {
#pragma unroll
    for (int m = 0; m < 16; m++) a[m] = 0.f;
    int j = j0;
    // peel to 16B alignment of index/weight arrays
    for (; j < j1 && (j & 3); j++) {
        int   s0 = __ldg(&g_esrc[j]);
        float v0 = __ldg(&g_eval[j]);
        const uint4* r0 = Sb + (size_t)s0 * 64;
        fma_bf16x2(a, v0, r0[0], r0[32]);
    }
    for (; j + 3 < j1; j += 4) {
        int4   ss = *(const int4*)&g_esrc[j];     // vectorized index load
        float4 vv = *(const float4*)&g_eval[j];   // vectorized weight load
        const uint4* r0 = Sb + (size_t)ss.x * 64;
        const uint4* r1 = Sb + (size_t)ss.y * 64;
        const uint4* r2 = Sb + (size_t)ss.z * 64;
        const uint4* r3 = Sb + (size_t)ss.w * 64;
        uint4 x00 = r0[0], x01 = r0[32];
        uint4 x10 = r1[0], x11 = r1[32];
        uint4 x20 = r2[0], x21 = r2[32];
        uint4 x30 = r3[0], x31 = r3[32];
        fma_bf16x2(a, vv.x, x00, x01);
        fma_bf16x2(a, vv.y, x10, x11);
        fma_bf16x2(a, vv.z, x20, x21);
        fma_bf16x2(a, vv.w, x30, x31);
    }
    for (; j < j1; j++) {
        int   s0 = __ldg(&g_esrc[j]);
        float v0 = __ldg(&g_eval[j]);
        const uint4* r0 = Sb + (size_t)s0 * 64;
        fma_bf16x2(a, v0, r0[0], r0[32]);
    }
}

// ---- layer-0 gather: H16[node] = bf16(relu(sum adj*S16[src] + b0)) ----
__global__ void __launch_bounds__(256)
gather_relu_k(const __nv_bfloat16* __restrict__ S16, __nv_bfloat16* __restrict__ H16,
              const float* __restrict__ bias)
{
    int w = threadIdx.x >> 5, lane = threadIdx.x & 31;
    int node = blockIdx.x * 8 + w;
    float a[16];
    gather_row16((const uint4*)S16 + lane, g_off[node], g_off[node + 1], a);
    float4 bv[4];
    bv[0] = __ldg((const float4*)bias + 2 * lane);
    bv[1] = __ldg((const float4*)bias + 2 * lane + 1);
    bv[2] = __ldg((const float4*)bias + 64 + 2 * lane);
    bv[3] = __ldg((const float4*)bias + 64 + 2 * lane + 1);
    const float* bb = (const float*)bv;
    uint4 o0, o1;
    uint32_t* p0 = (uint32_t*)&o0;
    uint32_t* p1 = (uint32_t*)&o1;
#pragma unroll
    for (int k = 0; k < 4; k++) {
        float e0 = fmaxf(a[2 * k]     + bb[2 * k], 0.f);
        float e1 = fmaxf(a[2 * k + 1] + bb[2 * k + 1], 0.f);
        p0[k] = pack_bf2(e0, e1);
        e0 = fmaxf(a[8 + 2 * k]     + bb[8 + 2 * k], 0.f);
        e1 = fmaxf(a[8 + 2 * k + 1] + bb[8 + 2 * k + 1], 0.f);
        p1[k] = pack_bf2(e0, e1);
    }
    *((uint4*)H16 + (size_t)node * 64 + lane)      = o0;
    *((uint4*)H16 + (size_t)node * 64 + 32 + lane) = o1;
}

// ---- edge pool: P0[g] = (1/64) * sum_{e: dst in graph g} adj_e * H16[src_e] ----
__global__ void __launch_bounds__(256)
edgepool_k(const __nv_bfloat16* __restrict__ H16, float* __restrict__ P0)
{
    __shared__ float4 red[8][128];
    int g = blockIdx.x;
    int w = threadIdx.x >> 5, lane = threadIdx.x & 31;
    int j0 = g_off[g * 64], j1 = g_off[g * 64 + 64];
    float a[16];
#pragma unroll
    for (int m = 0; m < 16; m++) a[m] = 0.f;
    const uint4* Hb = (const uint4*)H16 + lane;
    int j = j0 + w;
    for (; j + 8 < j1; j += 16) {
        int   s0 = __ldg(&g_esrc[j]);
        int   s1 = __ldg(&g_esrc[j + 8]);
        float v0 = __ldg(&g_eval[j]);
        float v1 = __ldg(&g_eval[j + 8]);
        const uint4* r0 = Hb + (size_t)s0 * 64;
        const uint4* r1 = Hb + (size_t)s1 * 64;
        uint4 x00 = r0[0], x01 = r0[32];
        uint4 x10 = r1[0], x11 = r1[32];
        fma_bf16x2(a, v0, x00, x01);
        fma_bf16x2(a, v1, x10, x11);
    }
    if (j < j1) {
        int   s0 = __ldg(&g_esrc[j]);
        float v0 = __ldg(&g_eval[j]);
        const uint4* r0 = Hb + (size_t)s0 * 64;
        fma_bf16x2(a, v0, r0[0], r0[32]);
    }
    red[w][2 * lane]          = make_float4(a[0], a[1], a[2], a[3]);
    red[w][2 * lane + 1]      = make_float4(a[4], a[5], a[6], a[7]);
    red[w][64 + 2 * lane]     = make_float4(a[8], a[9], a[10], a[11]);
    red[w][64 + 2 * lane + 1] = make_float4(a[12], a[13], a[14], a[15]);
    __syncthreads();
    if (threadIdx.x < 128) {
        int c4 = threadIdx.x;
        float4 s = red[0][c4];
#pragma unroll
        for (int q = 1; q < 8; q++) {
            float4 t = red[q][c4];
            s.x += t.x; s.y += t.y; s.z += t.z; s.w += t.w;
        }
        s.x *= (1.f / 64.f); s.y *= (1.f / 64.f);
        s.z *= (1.f / 64.f); s.w *= (1.f / 64.f);
        ((float4*)P0)[(size_t)g * 128 + c4] = s;
    }
}

// ======== wmma bf16x2 GEMM (A = hi+lo, B = hi), 2 CTAs/SM, streamed B frags ========
// CTA 128(M) x 128(N); 8 warps as 4(m) x 2(n); warp tile 32x64; BK=32; bf16 output.
static constexpr int LDA   = 40;
static constexpr int A_TSZ = 128 * LDA;                  // 5120 elems per tile
static constexpr int STG   = 3 * A_TSZ;                  // A-hi, A-lo, B-hi
static constexpr int SMEM_GEMM = 2 * STG * 2;            // 61440 bytes
__device__ __forceinline__ void cp16(uint32_t s, const void* g) {
    asm volatile("cp.async.cg.shared.global [%0], [%1], 16;" :: "r"(s), "l"(g));
}
__global__ void __launch_bounds__(256, 2)
gemm_bf2(const __nv_bfloat16* __restrict__ AH, const __nv_bfloat16* __restrict__ AL,
         const __nv_bfloat16* __restrict__ WT, __nv_bfloat16* __restrict__ C16)
{
    extern __shared__ __nv_bfloat16 sm[];
    const uint32_t smb = (uint32_t)__cvta_generic_to_shared(sm);
    const int tid = threadIdx.x;
    const int wid = tid >> 5;
    const int lane = tid & 31;
    const int m0 = blockIdx.y * 128;
    const int n0 = blockIdx.x * 128;
    const int wm = (wid >> 1) * 32;
    const int wn = (wid & 1) * 64;

    auto load_stage = [&](int kc, int s) {
        const uint32_t sb = smb + s * STG * 2;
#pragma unroll
        for (int t = 0; t < 2; t++) {
            const __nv_bfloat16* src = t ? AL : AH;
#pragma unroll
            for (int it = 0; it < 2; it++) {
                int c = tid + it * 256;
                int row = c >> 2, seg = c & 3;
                cp16(sb + (t * A_TSZ + row * LDA + seg * 8) * 2,
                     src + (size_t)(m0 + row) * DIM + kc * 32 + seg * 8);
            }
        }
#pragma unroll
        for (int it = 0; it < 2; it++) {
            int c = tid + it * 256;
            int row = c >> 2, seg = c & 3;
            cp16(sb + (2 * A_TSZ + row * LDA + seg * 8) * 2,
                 WT + (size_t)(n0 + row) * DIM + kc * 32 + seg * 8);
        }
        asm volatile("cp.async.commit_group;");
    };

    wmma::fragment<wmma::accumulator, 16, 16, 16, float> acc[2][4];
#pragma unroll
    for (int i = 0; i < 2; i++)
#pragma unroll
        for (int j = 0; j < 4; j++) wmma::fill_fragment(acc[i][j], 0.f);

    load_stage(0, 0);

    for (int kc = 0; kc < DIM / 32; kc++) {
        const int st = kc & 1;
        asm volatile("cp.async.wait_group 0;");
        __syncthreads();
        if (kc + 1 < DIM / 32) load_stage(kc + 1, st ^ 1);

        const __nv_bfloat16* Ah = &sm[st * STG];
        const __nv_bfloat16* Al = Ah + A_TSZ;
        const __nv_bfloat16* Bh = Ah + 2 * A_TSZ;
#pragma unroll
        for (int ks = 0; ks < 2; ks++) {
            const int kk = ks * 16;
            wmma::fragment<wmma::matrix_a, 16, 16, 16, __nv_bfloat16, wmma::row_major> ah[2], al[2];
#pragma unroll
            for (int i = 0; i < 2; i++) {
                wmma::load_matrix_sync(ah[i], Ah + (wm + 16 * i) * LDA + kk, LDA);
                wmma::load_matrix_sync(al[i], Al + (wm + 16 * i) * LDA + kk, LDA);
            }
#pragma unroll
            for (int j = 0; j < 4; j++) {      // stream one B fragment at a time
                wmma::fragment<wmma::matrix_b, 16, 16, 16, __nv_bfloat16, wmma::col_major> bh;
                wmma::load_matrix_sync(bh, Bh + (wn + 16 * j) * LDA + kk, LDA);
#pragma unroll
                for (int i = 0; i < 2; i++) {
                    wmma::mma_sync(acc[i][j], ah[i], bh, acc[i][j]);
                    wmma::mma_sync(acc[i][j], al[i], bh, acc[i][j]);
                }
            }
        }
    }

    // bf16 epilogue via per-warp smem staging (16x64 fp32 = 4KB per warp)
    __syncthreads();
    float* stage = reinterpret_cast<float*>(sm) + wid * 1024;
#pragma unroll
    for (int i = 0; i < 2; i++) {
#pragma unroll
        for (int j = 0; j < 4; j++)
            wmma::store_matrix_sync(stage + 16 * j, acc[i][j], 64, wmma::mem_row_major);
        __syncwarp();
#pragma unroll
        for (int q = 0; q < 4; q++) {
            int chunk = lane + 32 * q;           // 0..127
            int r = chunk >> 3, p = chunk & 7;   // 16 rows x 8 chunks
            float4 f0 = *(float4*)(stage + r * 64 + p * 8);
            float4 f1 = *(float4*)(stage + r * 64 + p * 8 + 4);
            uint4 hv;
            ((uint32_t*)&hv)[0] = pack_bf2(f0.x, f0.y);
            ((uint32_t*)&hv)[1] = pack_bf2(f0.z, f0.w);
            ((uint32_t*)&hv)[2] = pack_bf2(f1.x, f1.y);
            ((uint32_t*)&hv)[3] = pack_bf2(f1.z, f1.w);
            *(uint4*)(C16 + (size_t)(m0 + wm + 16 * i + r) * DIM + n0 + wn + p * 8) = hv;
        }
        __syncwarp();
    }
}

// ================= small fp32 GEMM core, cp.async double-buffered =================
// 32x64 tile, 256 threads (16x16, 2x4 micro), BK=32, K=DIM=512.
struct SmemS { float As[2][32][36]; float Bs[2][32][64]; };

template<int ACT, bool CA, bool EXPAND>
__device__ __forceinline__ void small_gemm_core(
    SmemS& smem,
    const float* __restrict__ A, const float* __restrict__ B,
    const float* __restrict__ bias, const float* __restrict__ cadd,
    float* __restrict__ C, int bm0, int bn0)
{
    const int tid = threadIdx.x;
    const int tx = tid & 15, ty = tid >> 4;
    float acc[2][4];
#pragma unroll
    for (int i = 0; i < 2; i++)
#pragma unroll
        for (int j = 0; j < 4; j++) acc[i][j] = 0.f;

    auto load = [&](int kc, int s) {
        {
            int c = tid;
            int row = c >> 3, seg = c & 7;
            cp16((uint32_t)__cvta_generic_to_shared(&smem.As[s][row][seg * 4]),
                 A + (size_t)(bm0 + row) * DIM + kc * 32 + seg * 4);
        }
#pragma unroll
        for (int it = 0; it < 2; it++) {
            int c = tid + it * 256;
            int row = c >> 4, seg = c & 15;
            cp16((uint32_t)__cvta_generic_to_shared(&smem.Bs[s][row][seg * 4]),
                 B + (size_t)(kc * 32 + row) * DIM + bn0 + seg * 4);
        }
        asm volatile("cp.async.commit_group;");
    };

    load(0, 0);
    for (int kc = 0; kc < DIM / 32; kc++) {
        const int st = kc & 1;
        asm volatile("cp.async.wait_group 0;");
        __syncthreads();
        if (kc + 1 < DIM / 32) load(kc + 1, st ^ 1);
#pragma unroll
        for (int kk = 0; kk < 32; kk++) {
            float ra[2], rb[4];
#pragma unroll
            for (int i = 0; i < 2; i++) ra[i] = smem.As[st][ty * 2 + i][kk];
            *(float4*)rb = *(const float4*)&smem.Bs[st][kk][tx * 4];
#pragma unroll
            for (int i = 0; i < 2; i++)
#pragma unroll
                for (int j = 0; j < 4; j++)
                    acc[i][j] = fmaf(ra[i], rb[j], acc[i][j]);
        }
    }

#pragma unroll
    for (int i = 0; i < 2; i++) {
        int m = bm0 + ty * 2 + i;
        int n = bn0 + tx * 4;
        float4 v = make_float4(acc[i][0], acc[i][1], acc[i][2], acc[i][3]);
        float4 bv = *(const float4*)(bias + n);
        v.x += bv.x; v.y += bv.y; v.z += bv.z; v.w += bv.w;
        if (ACT == 1) {
            v.x = fmaxf(v.x, 0.f); v.y = fmaxf(v.y, 0.f);
            v.z = fmaxf(v.z, 0.f); v.w = fmaxf(v.w, 0.f);
        }
        if (ACT == 2) {
            v.x = 1.f / (1.f + __expf(-v.x)); v.y = 1.f / (1.f + __expf(-v.y));
            v.z = 1.f / (1.f + __expf(-v.z)); v.w = 1.f / (1.f + __expf(-v.w));
        }
        if (CA) {
            float4 av = *(const float4*)(cadd + (size_t)m * DIM + n);
            v.x += av.x; v.y += av.y; v.z += av.z; v.w += av.w;
        }
        if (EXPAND) {
            float* base = C + (size_t)m * 64 * DIM + n;
#pragma unroll 8
            for (int rep = 0; rep < 64; rep++)
                *(float4*)(base + (size_t)rep * DIM) = v;
        } else {
            *(float4*)(C + (size_t)m * DIM + n) = v;
        }
    }
}

template<int ACT>
__global__ void __launch_bounds__(256)
gemm_s(const float* __restrict__ A, const float* __restrict__ B,
       const float* __restrict__ bias, float* __restrict__ C)
{
    __shared__ SmemS smem;
    small_gemm_core<ACT, false, false>(smem, A, B, bias, nullptr, C,
                                       blockIdx.y * 32, blockIdx.x * 64);
}

__global__ void __launch_bounds__(256)
gemm_dual(const float* __restrict__ A,
          const float* __restrict__ B0, const float* __restrict__ bias0, float* __restrict__ C0,
          const float* __restrict__ B1, const float* __restrict__ bias1, float* __restrict__ C1)
{
    __shared__ SmemS smem;
    if (blockIdx.z == 0)
        small_gemm_core<1, false, false>(smem, A, B0, bias0, nullptr, C0,
                                         blockIdx.y * 32, blockIdx.x * 64);
    else
        small_gemm_core<0, false, false>(smem, A, B1, bias1, nullptr, C1,
                                         blockIdx.y * 32, blockIdx.x * 64);
}

__global__ void __launch_bounds__(256)
gemm_final(const float* __restrict__ A, const float* __restrict__ B,
           const float* __restrict__ bias, const float* __restrict__ cadd,
           float* __restrict__ out)
{
    __shared__ SmemS smem;
    small_gemm_core<1, true, true>(smem, A, B, bias, cadd, out,
                                   blockIdx.y * 32, blockIdx.x * 64);
}

// ---------------- launch ----------------
extern "C" void kernel_launch(void* const* d_in, const int* in_sizes, int n_in,
                              void* d_out, int out_size)
{
    const float* feat = (const float*)d_in[0];
    const int*   src  = (const int*)  d_in[1];
    const int*   dst  = (const int*)  d_in[2];
    const float* adj  = (const float*)d_in[3];
    const float* W0   = (const float*)d_in[5];
    const float* b0   = (const float*)d_in[6];
    const float* W1   = (const float*)d_in[7];
    const float* b1   = (const float*)d_in[8];
    const float* gW1  = (const float*)d_in[9];
    const float* gb1  = (const float*)d_in[10];
    const float* gW2  = (const float*)d_in[11];
    const float* gb2  = (const float*)d_in[12];
    const float* gW3  = (const float*)d_in[13];
    const float* gb3  = (const float*)d_in[14];
    const float* gWs  = (const float*)d_in[15];
    const float* gbs  = (const float*)d_in[16];
    float* out = (float*)d_out;

    float *P0, *GS, *Z1, *Z2, *ZS;
    __nv_bfloat16 *S16, *H16, *WT0, *AH, *AL;
    cudaGetSymbolAddress((void**)&S16, g_S16);
    cudaGetSymbolAddress((void**)&H16, g_H16);
    cudaGetSymbolAddress((void**)&P0,  g_P0);
    cudaGetSymbolAddress((void**)&GS,  g_GS);
    cudaGetSymbolAddress((void**)&Z1,  g_Z1);
    cudaGetSymbolAddress((void**)&Z2,  g_Z2);
    cudaGetSymbolAddress((void**)&ZS,  g_ZS);
    cudaGetSymbolAddress((void**)&WT0, g_WT0);
    cudaGetSymbolAddress((void**)&AH,  g_AH);
    cudaGetSymbolAddress((void**)&AL,  g_AL);

    cudaFuncSetAttribute(gemm_bf2, cudaFuncAttributeMaxDynamicSharedMemorySize, SMEM_GEMM);

    dim3 gw(DIM / 128, N_NODES / 128);
    dim3 gsm(DIM / 64, NGRAPH / 32);
    dim3 gdual(DIM / 64, NGRAPH / 32, 2);

    // 1: fused prep (W0 hi transpose + feat split + deg zero)
    prep_all<<<17440, 256>>>(W0, WT0, feat, AH, AL);
    // 2-3: CSR histogram + scan
    hist_k<<<E_EDGES / 256, 256>>>(dst);
    scan_k<<<1, 1024>>>();
    // 4: GCN layer 0 GEMM (profiled slot)
    gemm_bf2<<<gw, 256, SMEM_GEMM>>>(AH, AL, WT0, S16);
    // 5: CSR scatter
    scat_k<<<E_EDGES / 256, 256>>>(dst, src, adj);
    // 6: H16 = bf16(relu(A_hat@S16 + b0))
    gather_relu_k<<<N_NODES / 8, 256>>>(S16, H16, b0);
    // 7: layer-1 collapsed through pooling
    edgepool_k<<<NGRAPH, 256>>>(H16, P0);
    // 8-11: pooled tail
    gemm_s<2><<<gsm, 256>>>(P0, W1, b1, GS);                       // GS = sigmoid(P0@W1+b1)
    gemm_dual<<<gdual, 256>>>(GS, gW1, gb1, Z1, gWs, gbs, ZS);     // Z1 & shortcut ZS
    gemm_s<1><<<gsm, 256>>>(Z1, gW2, gb2, Z2);                     // Z2
    gemm_final<<<gsm, 256>>>(Z2, gW3, gb3, ZS, out);               // relu(+b3)+ZS, expand
}